// round 5
// baseline (speedup 1.0000x reference)
#include <cuda_runtime.h>
#include <cuda_fp16.h>
#include <cstdint>

// Problem dims (fixed by the dataset)
#define M_DIM 8192      // 4 * 2048
#define N_DIM 4096      // OUT_FEATURES
#define K_DIM 4096      // IN_FEATURES

// GEMM tiling
#define BM 128
#define BN 128
#define BK 32
#define LDS_PAD 8                    // halves of padding per smem row
#define LDR (BK + LDS_PAD)           // 40 halves = 80 bytes per row (16B aligned, conflict-free ldmatrix)
#define K_TILES (K_DIM / BK)         // 128

// Scratch (allocation-free: __device__ globals)
__device__ __half g_Wh[(size_t)N_DIM * K_DIM];   // 32 MB, row-major [N][K]
__device__ __half g_Xh[(size_t)M_DIM * K_DIM];   // 64 MB, row-major [M][K]

__constant__ float c_nf4[16] = {
    -1.0f, -0.6961928009986877f, -0.5250730514526367f, -0.39491748809814453f,
    -0.28444138169288635f, -0.18477343022823334f, -0.09105003625154495f, 0.0f,
    0.07958029955625534f, 0.16093020141124725f, 0.24611230194568634f,
    0.33791524171829224f, 0.44070982933044434f, 0.5626170039176941f,
    0.7229568362236023f, 1.0f};

// ---------------------------------------------------------------------------
// Kernel 1: x (fp32) -> Xh (fp16), vectorized by 4
// ---------------------------------------------------------------------------
__global__ void convert_x_kernel(const float* __restrict__ x) {
    size_t i = ((size_t)blockIdx.x * blockDim.x + threadIdx.x) * 4;
    if (i >= (size_t)M_DIM * K_DIM) return;
    float4 v = *reinterpret_cast<const float4*>(x + i);
    __half2 h0 = __floats2half2_rn(v.x, v.y);
    __half2 h1 = __floats2half2_rn(v.z, v.w);
    uint2 out;
    out.x = *reinterpret_cast<uint32_t*>(&h0);
    out.y = *reinterpret_cast<uint32_t*>(&h1);
    *reinterpret_cast<uint2*>(&g_Xh[i]) = out;
}

// ---------------------------------------------------------------------------
// Kernel 2: NF4 dequant: packed (int32 bytes, [N][K/2]) -> Wh fp16 [N][K]
// high nibble -> k=2i, low nibble -> k=2i+1
// ---------------------------------------------------------------------------
__global__ void dequant_kernel(const int* __restrict__ packed,
                               const float* __restrict__ absmax) {
    int idx = blockIdx.x * blockDim.x + threadIdx.x;       // over N*K/2
    if (idx >= N_DIM * (K_DIM / 2)) return;
    int n = idx / (K_DIM / 2);
    int b = packed[idx];
    float a = absmax[n];
    __half2 v = __floats2half2_rn(c_nf4[(b >> 4) & 15] * a, c_nf4[b & 15] * a);
    *reinterpret_cast<__half2*>(&g_Wh[(size_t)idx * 2]) = v;
}

// ---------------------------------------------------------------------------
// Kernel 3: GEMM  out[m,n] = sum_k Xh[m,k] * Wh[n,k] + bias[n]
// 256 threads = 8 warps, 4(m) x 2(n) warp grid; warp tile 32x64
// mma.sync.m16n8k16 f16 inputs, f32 accumulate
// ---------------------------------------------------------------------------
__device__ __forceinline__ void cp_async16(void* smem, const void* gmem) {
    uint32_t s = (uint32_t)__cvta_generic_to_shared(smem);
    asm volatile("cp.async.cg.shared.global [%0], [%1], 16;\n" :: "r"(s), "l"(gmem));
}
__device__ __forceinline__ void cp_commit() {
    asm volatile("cp.async.commit_group;\n");
}
__device__ __forceinline__ void ldsm_x4(uint32_t& r0, uint32_t& r1, uint32_t& r2,
                                        uint32_t& r3, const void* p) {
    uint32_t a = (uint32_t)__cvta_generic_to_shared(p);
    asm volatile("ldmatrix.sync.aligned.m8n8.x4.shared.b16 {%0,%1,%2,%3}, [%4];\n"
                 : "=r"(r0), "=r"(r1), "=r"(r2), "=r"(r3) : "r"(a));
}
__device__ __forceinline__ void mma_16816(float* c, const uint32_t* a, const uint32_t* b) {
    asm volatile(
        "mma.sync.aligned.m16n8k16.row.col.f32.f16.f16.f32 "
        "{%0,%1,%2,%3}, {%4,%5,%6,%7}, {%8,%9}, {%0,%1,%2,%3};\n"
        : "+f"(c[0]), "+f"(c[1]), "+f"(c[2]), "+f"(c[3])
        : "r"(a[0]), "r"(a[1]), "r"(a[2]), "r"(a[3]), "r"(b[0]), "r"(b[1]));
}

__global__ __launch_bounds__(256) void gemm_kernel(float* __restrict__ out,
                                                   const float* __restrict__ bias) {
    __shared__ __half As[2][BM][LDR];
    __shared__ __half Bs[2][BN][LDR];

    const int tid = threadIdx.x;
    const int lane = tid & 31;
    const int warp = tid >> 5;
    const int wm = warp >> 1;            // 0..3 -> m offset
    const int wn = warp & 1;             // 0..1 -> n offset
    const int m_warp = wm * 32;
    const int n_warp = wn * 64;

    const int m0 = blockIdx.y * BM;
    const int n0 = blockIdx.x * BN;

    float acc[2][8][4];
#pragma unroll
    for (int i = 0; i < 2; i++)
#pragma unroll
        for (int j = 0; j < 8; j++)
#pragma unroll
            for (int c = 0; c < 4; c++) acc[i][j][c] = 0.0f;

    // --- stage loader: 512 16B chunks each for A and B, 2 per thread each ---
    auto load_stage = [&](int s, int kt) {
        const int k0 = kt * BK;
#pragma unroll
        for (int c = tid; c < 512; c += 256) {
            int row = c >> 2;
            int cg = c & 3;
            cp_async16(&As[s][row][cg * 8],
                       &g_Xh[(size_t)(m0 + row) * K_DIM + k0 + cg * 8]);
        }
#pragma unroll
        for (int c = tid; c < 512; c += 256) {
            int row = c >> 2;
            int cg = c & 3;
            cp_async16(&Bs[s][row][cg * 8],
                       &g_Wh[(size_t)(n0 + row) * K_DIM + k0 + cg * 8]);
        }
    };

    load_stage(0, 0);
    cp_commit();

    for (int kt = 0; kt < K_TILES; kt++) {
        const int s = kt & 1;
        if (kt + 1 < K_TILES) {
            load_stage((kt + 1) & 1, kt + 1);
            cp_commit();
            asm volatile("cp.async.wait_group 1;\n");
        } else {
            asm volatile("cp.async.wait_group 0;\n");
        }
        __syncthreads();

#pragma unroll
        for (int kk = 0; kk < BK; kk += 16) {
            // A fragments: 2 m16 tiles
            uint32_t afrag[2][4];
#pragma unroll
            for (int im = 0; im < 2; im++) {
                const __half* p =
                    &As[s][m_warp + im * 16 + (lane & 15)][kk + (lane >> 4) * 8];
                ldsm_x4(afrag[im][0], afrag[im][1], afrag[im][2], afrag[im][3], p);
            }
            // B fragments: 8 n8 tiles via 4 non-trans x4 loads.
            // Bs is [n][k]; feeding n-row pointers to plain ldmatrix gives
            // thread l element (n = l/4, k = (l%4)*2+i) == mma B fragment.
            // Matrix grouping per x4: {ntile jp k0-7, ntile jp k8-15,
            //                          ntile jp+1 k0-7, ntile jp+1 k8-15}
            uint32_t bfrag[8][2];
#pragma unroll
            for (int jp = 0; jp < 4; jp++) {
                int n_row = n_warp + jp * 16 + (lane & 7) + ((lane >> 4) << 3);
                int k_col = kk + (((lane >> 3) & 1) << 3);
                const __half* p = &Bs[s][n_row][k_col];
                ldsm_x4(bfrag[2 * jp][0], bfrag[2 * jp][1],
                        bfrag[2 * jp + 1][0], bfrag[2 * jp + 1][1], p);
            }
#pragma unroll
            for (int im = 0; im < 2; im++)
#pragma unroll
                for (int jn = 0; jn < 8; jn++)
                    mma_16816(acc[im][jn], afrag[im], bfrag[jn]);
        }
        __syncthreads();
    }

    // --- epilogue: + bias, fp32 stores ---
    const int m_base = m0 + m_warp;
    const int n_base = n0 + n_warp;
#pragma unroll
    for (int jn = 0; jn < 8; jn++) {
        int col = n_base + jn * 8 + (lane & 3) * 2;
        float b0 = bias[col];
        float b1 = bias[col + 1];
#pragma unroll
        for (int im = 0; im < 2; im++) {
            int row0 = m_base + im * 16 + (lane >> 2);
            float2 v0 = make_float2(acc[im][jn][0] + b0, acc[im][jn][1] + b1);
            float2 v1 = make_float2(acc[im][jn][2] + b0, acc[im][jn][3] + b1);
            *reinterpret_cast<float2*>(&out[(size_t)row0 * N_DIM + col]) = v0;
            *reinterpret_cast<float2*>(&out[(size_t)(row0 + 8) * N_DIM + col]) = v1;
        }
    }
}

// ---------------------------------------------------------------------------
// Launch
// ---------------------------------------------------------------------------
extern "C" void kernel_launch(void* const* d_in, const int* in_sizes, int n_in,
                              void* d_out, int out_size) {
    const float* x      = (const float*)d_in[0];   // (4,2048,4096) f32
    const int*   packed = (const int*)d_in[1];     // (4096,2048) int32 bytes
    const float* absmax = (const float*)d_in[2];   // (4096,) f32
    const float* bias   = (const float*)d_in[3];   // (4096,) f32
    float* out = (float*)d_out;                    // (4,2048,4096) f32

    {   // x -> fp16
        int total = (M_DIM * K_DIM) / 4;           // 8,388,608 float4 groups
        convert_x_kernel<<<(total + 255) / 256, 256>>>(x);
    }
    {   // NF4 dequant -> fp16 W
        int total = N_DIM * (K_DIM / 2);           // 8,388,608 bytes
        dequant_kernel<<<(total + 255) / 256, 256>>>(packed, absmax);
    }
    {   // GEMM
        dim3 grid(N_DIM / BN, M_DIM / BM);         // (32, 64)
        gemm_kernel<<<grid, 256>>>(out, bias);
    }
}

// round 7
// speedup vs baseline: 1.1760x; 1.1760x over previous
#include <cuda_runtime.h>
#include <cuda_fp16.h>
#include <cstdint>

// Problem dims (fixed by the dataset)
#define M_DIM 8192      // 4 * 2048
#define N_DIM 4096      // OUT_FEATURES
#define K_DIM 4096      // IN_FEATURES

// GEMM tiling (mma.sync path — sm_103 base target, no tcgen05 available)
#define BM 256
#define BN 128
#define BK 64
#define LDS_PAD 8                     // halves of pad per row
#define LDR (BK + LDS_PAD)            // 72 halves = 144 B/row (16B aligned)
#define K_TILES (K_DIM / BK)          // 64
#define STAGES 3
#define THREADS 512                   // 16 warps: 4(m) x 4(n), warp tile 64x32

// Dynamic smem layout (halves)
#define A_ST_H (BM * LDR)             // 18432 halves = 36864 B
#define B_ST_H (BN * LDR)             // 9216 halves  = 18432 B
#define SMEM_HALVES (STAGES * (A_ST_H + B_ST_H))     // 82944 halves
#define SMEM_BYTES (SMEM_HALVES * 2)                 // 165888 B

// Scratch (allocation-free: __device__ globals)
__device__ __half g_Wh[(size_t)N_DIM * K_DIM];   // 32 MB, row-major [N][K]
__device__ __half g_Xh[(size_t)M_DIM * K_DIM];   // 64 MB, row-major [M][K]

__constant__ float c_nf4[16] = {
    -1.0f, -0.6961928009986877f, -0.5250730514526367f, -0.39491748809814453f,
    -0.28444138169288635f, -0.18477343022823334f, -0.09105003625154495f, 0.0f,
    0.07958029955625534f, 0.16093020141124725f, 0.24611230194568634f,
    0.33791524171829224f, 0.44070982933044434f, 0.5626170039176941f,
    0.7229568362236023f, 1.0f};

// ---------------------------------------------------------------------------
// Kernel 1: x (fp32) -> Xh (fp16)
// ---------------------------------------------------------------------------
__global__ void convert_x_kernel(const float* __restrict__ x) {
    size_t i = ((size_t)blockIdx.x * blockDim.x + threadIdx.x) * 4;
    if (i >= (size_t)M_DIM * K_DIM) return;
    float4 v = *reinterpret_cast<const float4*>(x + i);
    __half2 h0 = __floats2half2_rn(v.x, v.y);
    __half2 h1 = __floats2half2_rn(v.z, v.w);
    uint2 o;
    o.x = *reinterpret_cast<uint32_t*>(&h0);
    o.y = *reinterpret_cast<uint32_t*>(&h1);
    *reinterpret_cast<uint2*>(&g_Xh[i]) = o;
}

// ---------------------------------------------------------------------------
// Kernel 2: NF4 dequant -> Wh fp16 [N][K]
// ---------------------------------------------------------------------------
__global__ void dequant_kernel(const int* __restrict__ packed,
                               const float* __restrict__ absmax) {
    int idx = blockIdx.x * blockDim.x + threadIdx.x;       // over N*K/2
    if (idx >= N_DIM * (K_DIM / 2)) return;
    int n = idx / (K_DIM / 2);
    int b = packed[idx];
    float a = absmax[n];
    __half2 v = __floats2half2_rn(c_nf4[(b >> 4) & 15] * a, c_nf4[b & 15] * a);
    *reinterpret_cast<__half2*>(&g_Wh[(size_t)idx * 2]) = v;
}

// ---------------------------------------------------------------------------
// mma.sync GEMM helpers
// ---------------------------------------------------------------------------
__device__ __forceinline__ void cp_async16(void* smem, const void* gmem) {
    uint32_t s = (uint32_t)__cvta_generic_to_shared(smem);
    asm volatile("cp.async.cg.shared.global [%0], [%1], 16;\n" :: "r"(s), "l"(gmem));
}
__device__ __forceinline__ void cp_commit() {
    asm volatile("cp.async.commit_group;\n" ::: "memory");
}
__device__ __forceinline__ void ldsm_x4(uint32_t& r0, uint32_t& r1, uint32_t& r2,
                                        uint32_t& r3, const void* p) {
    uint32_t a = (uint32_t)__cvta_generic_to_shared(p);
    asm volatile("ldmatrix.sync.aligned.m8n8.x4.shared.b16 {%0,%1,%2,%3}, [%4];\n"
                 : "=r"(r0), "=r"(r1), "=r"(r2), "=r"(r3) : "r"(a));
}
__device__ __forceinline__ void mma_16816(float* c, const uint32_t* a, const uint32_t* b) {
    asm volatile(
        "mma.sync.aligned.m16n8k16.row.col.f32.f16.f16.f32 "
        "{%0,%1,%2,%3}, {%4,%5,%6,%7}, {%8,%9}, {%0,%1,%2,%3};\n"
        : "+f"(c[0]), "+f"(c[1]), "+f"(c[2]), "+f"(c[3])
        : "r"(a[0]), "r"(a[1]), "r"(a[2]), "r"(a[3]), "r"(b[0]), "r"(b[1]));
}

// ---------------------------------------------------------------------------
// Kernel 3: GEMM  out[m,n] = sum_k Xh[m,k]*Wh[n,k] + bias[n]
// 512 threads = 16 warps (4m x 4n), warp tile 64x32.
// BK=64, 3-stage cp.async pipeline, ONE __syncthreads per K-chunk.
// ---------------------------------------------------------------------------
__global__ __launch_bounds__(THREADS, 1) void gemm_kernel(
        float* __restrict__ out, const float* __restrict__ bias) {
    extern __shared__ __half sm[];
    // A stages: sm + s*A_ST_H ; B stages: sm + STAGES*A_ST_H + s*B_ST_H
    __half* Abase = sm;
    __half* Bbase = sm + STAGES * A_ST_H;

    const int tid = threadIdx.x;
    const int lane = tid & 31;
    const int warp = tid >> 5;
    const int m_off = (warp >> 2) * 64;     // 0,64,128,192
    const int n_off = (warp & 3) * 32;      // 0,32,64,96

    const int m0 = blockIdx.y * BM;
    const int n0 = blockIdx.x * BN;

    float acc[4][4][4];
#pragma unroll
    for (int i = 0; i < 4; i++)
#pragma unroll
        for (int j = 0; j < 4; j++)
#pragma unroll
            for (int c = 0; c < 4; c++) acc[i][j][c] = 0.0f;

    // stage loader: A 2048 chunks (256 rows x 8x16B), B 1024 chunks
    auto load_stage = [&](int s, int kt) {
        const int k0 = kt * BK;
        __half* As = Abase + s * A_ST_H;
        __half* Bs = Bbase + s * B_ST_H;
        const __half* Ag = g_Xh + (size_t)m0 * K_DIM + k0;
        const __half* Bg = g_Wh + (size_t)n0 * K_DIM + k0;
#pragma unroll
        for (int c = tid; c < 2048; c += THREADS) {
            int row = c >> 3, cg = c & 7;
            cp_async16(As + row * LDR + cg * 8, Ag + (size_t)row * K_DIM + cg * 8);
        }
#pragma unroll
        for (int c = tid; c < 1024; c += THREADS) {
            int row = c >> 3, cg = c & 7;
            cp_async16(Bs + row * LDR + cg * 8, Bg + (size_t)row * K_DIM + cg * 8);
        }
    };

    load_stage(0, 0); cp_commit();
    load_stage(1, 1); cp_commit();

    for (int kt = 0; kt < K_TILES; kt++) {
        const int s = kt % STAGES;
        if (kt == K_TILES - 1)
            asm volatile("cp.async.wait_group 0;\n" ::: "memory");
        else
            asm volatile("cp.async.wait_group 1;\n" ::: "memory");
        __syncthreads();
        // refill the stage last read at iter kt-1 with chunk kt+2
        if (kt + 2 < K_TILES) { load_stage((kt + 2) % STAGES, kt + 2); cp_commit(); }

        const __half* As = Abase + s * A_ST_H;
        const __half* Bs = Bbase + s * B_ST_H;

#pragma unroll
        for (int kk = 0; kk < BK; kk += 16) {
            // A: 4 m16 tiles
            uint32_t afrag[4][4];
#pragma unroll
            for (int im = 0; im < 4; im++) {
                const __half* p = As + (m_off + im * 16 + (lane & 15)) * LDR +
                                  kk + (lane >> 4) * 8;
                ldsm_x4(afrag[im][0], afrag[im][1], afrag[im][2], afrag[im][3], p);
            }
            // B: 4 n8 tiles via 2 non-trans x4 loads (Bs is [n][k])
            uint32_t bfrag[4][2];
#pragma unroll
            for (int jp = 0; jp < 2; jp++) {
                int n_row = n_off + jp * 16 + (lane & 7) + ((lane >> 4) << 3);
                int k_col = kk + (((lane >> 3) & 1) << 3);
                const __half* p = Bs + n_row * LDR + k_col;
                ldsm_x4(bfrag[2 * jp][0], bfrag[2 * jp][1],
                        bfrag[2 * jp + 1][0], bfrag[2 * jp + 1][1], p);
            }
#pragma unroll
            for (int im = 0; im < 4; im++)
#pragma unroll
                for (int jn = 0; jn < 4; jn++)
                    mma_16816(acc[im][jn], afrag[im], bfrag[jn]);
        }
    }

    // epilogue: + bias, fp32 stores
    const int m_base = m0 + m_off;
    const int n_base = n0 + n_off;
#pragma unroll
    for (int jn = 0; jn < 4; jn++) {
        int col = n_base + jn * 8 + (lane & 3) * 2;
        float b0 = bias[col];
        float b1 = bias[col + 1];
#pragma unroll
        for (int im = 0; im < 4; im++) {
            int row0 = m_base + im * 16 + (lane >> 2);
            float2 v0 = make_float2(acc[im][jn][0] + b0, acc[im][jn][1] + b1);
            float2 v1 = make_float2(acc[im][jn][2] + b0, acc[im][jn][3] + b1);
            *reinterpret_cast<float2*>(&out[(size_t)row0 * N_DIM + col]) = v0;
            *reinterpret_cast<float2*>(&out[(size_t)(row0 + 8) * N_DIM + col]) = v1;
        }
    }
}

// ---------------------------------------------------------------------------
// Launch
// ---------------------------------------------------------------------------
extern "C" void kernel_launch(void* const* d_in, const int* in_sizes, int n_in,
                              void* d_out, int out_size) {
    const float* x      = (const float*)d_in[0];   // (4,2048,4096) f32
    const int*   packed = (const int*)d_in[1];     // (4096,2048) int32 bytes
    const float* absmax = (const float*)d_in[2];   // (4096,) f32
    const float* bias   = (const float*)d_in[3];   // (4096,) f32
    float* out = (float*)d_out;                    // (4,2048,4096) f32

    {   // x -> fp16
        int total = (M_DIM * K_DIM) / 4;
        convert_x_kernel<<<(total + 255) / 256, 256>>>(x);
    }
    {   // NF4 dequant -> fp16 W
        int total = N_DIM * (K_DIM / 2);
        dequant_kernel<<<(total + 255) / 256, 256>>>(packed, absmax);
    }
    {   // GEMM (idempotent host-side attr set; no stream ops, capture-safe)
        cudaFuncSetAttribute(gemm_kernel,
                             cudaFuncAttributeMaxDynamicSharedMemorySize, SMEM_BYTES);
        dim3 grid(N_DIM / BN, M_DIM / BM);         // (32, 32)
        gemm_kernel<<<grid, THREADS, SMEM_BYTES>>>(out, bias);
    }
}

// round 9
// speedup vs baseline: 1.1803x; 1.0037x over previous
#include <cuda_runtime.h>
#include <cuda_fp16.h>
#include <cstdint>

// Problem dims (fixed by the dataset)
#define M_DIM 8192      // 4 * 2048
#define N_DIM 4096      // OUT_FEATURES
#define K_DIM 4096      // IN_FEATURES

// GEMM tiling (mma.sync path — sm_103 base target, no tcgen05 available)
#define BM 256
#define BN 128
#define BK 64
#define LDS_PAD 8                     // halves of pad per row
#define LDR (BK + LDS_PAD)            // 72 halves = 144 B/row (16B aligned, conflict-free)
#define K_TILES (K_DIM / BK)          // 64
#define STAGES 4
#define THREADS 256                   // 8 warps: 4(m) x 2(n), warp tile 64x64

// Dynamic smem layout (halves)
#define A_ST_H (BM * LDR)             // 18432 halves = 36864 B
#define B_ST_H (BN * LDR)             // 9216 halves  = 18432 B
#define SMEM_HALVES (STAGES * (A_ST_H + B_ST_H))     // 110592 halves
#define SMEM_BYTES (SMEM_HALVES * 2)                 // 221184 B

// Scratch (allocation-free: __device__ globals)
__device__ __half g_Wh[(size_t)N_DIM * K_DIM];   // 32 MB, row-major [N][K]
__device__ __half g_Xh[(size_t)M_DIM * K_DIM];   // 64 MB, row-major [M][K]

__constant__ float c_nf4[16] = {
    -1.0f, -0.6961928009986877f, -0.5250730514526367f, -0.39491748809814453f,
    -0.28444138169288635f, -0.18477343022823334f, -0.09105003625154495f, 0.0f,
    0.07958029955625534f, 0.16093020141124725f, 0.24611230194568634f,
    0.33791524171829224f, 0.44070982933044434f, 0.5626170039176941f,
    0.7229568362236023f, 1.0f};

// ---------------------------------------------------------------------------
// Kernel 1: x (fp32) -> Xh (fp16)
// ---------------------------------------------------------------------------
__global__ void convert_x_kernel(const float* __restrict__ x) {
    size_t i = ((size_t)blockIdx.x * blockDim.x + threadIdx.x) * 4;
    if (i >= (size_t)M_DIM * K_DIM) return;
    float4 v = *reinterpret_cast<const float4*>(x + i);
    __half2 h0 = __floats2half2_rn(v.x, v.y);
    __half2 h1 = __floats2half2_rn(v.z, v.w);
    uint2 o;
    o.x = *reinterpret_cast<uint32_t*>(&h0);
    o.y = *reinterpret_cast<uint32_t*>(&h1);
    *reinterpret_cast<uint2*>(&g_Xh[i]) = o;
}

// ---------------------------------------------------------------------------
// Kernel 2: NF4 dequant -> Wh fp16 [N][K]
// ---------------------------------------------------------------------------
__global__ void dequant_kernel(const int* __restrict__ packed,
                               const float* __restrict__ absmax) {
    int idx = blockIdx.x * blockDim.x + threadIdx.x;       // over N*K/2
    if (idx >= N_DIM * (K_DIM / 2)) return;
    int n = idx / (K_DIM / 2);
    int b = packed[idx];
    float a = absmax[n];
    __half2 v = __floats2half2_rn(c_nf4[(b >> 4) & 15] * a, c_nf4[b & 15] * a);
    *reinterpret_cast<__half2*>(&g_Wh[(size_t)idx * 2]) = v;
}

// ---------------------------------------------------------------------------
// mma.sync GEMM helpers
// ---------------------------------------------------------------------------
__device__ __forceinline__ void cp_async16(void* smem, const void* gmem) {
    uint32_t s = (uint32_t)__cvta_generic_to_shared(smem);
    asm volatile("cp.async.cg.shared.global [%0], [%1], 16;\n" :: "r"(s), "l"(gmem));
}
__device__ __forceinline__ void cp_commit() {
    asm volatile("cp.async.commit_group;\n" ::: "memory");
}
__device__ __forceinline__ void ldsm_x4(uint32_t& r0, uint32_t& r1, uint32_t& r2,
                                        uint32_t& r3, const void* p) {
    uint32_t a = (uint32_t)__cvta_generic_to_shared(p);
    asm volatile("ldmatrix.sync.aligned.m8n8.x4.shared.b16 {%0,%1,%2,%3}, [%4];\n"
                 : "=r"(r0), "=r"(r1), "=r"(r2), "=r"(r3) : "r"(a));
}
__device__ __forceinline__ void mma_16816(float* c, const uint32_t* a, const uint32_t* b) {
    asm volatile(
        "mma.sync.aligned.m16n8k16.row.col.f32.f16.f16.f32 "
        "{%0,%1,%2,%3}, {%4,%5,%6,%7}, {%8,%9}, {%0,%1,%2,%3};\n"
        : "+f"(c[0]), "+f"(c[1]), "+f"(c[2]), "+f"(c[3])
        : "r"(a[0]), "r"(a[1]), "r"(a[2]), "r"(a[3]), "r"(b[0]), "r"(b[1]));
}

// ---------------------------------------------------------------------------
// Kernel 3: GEMM  out[m,n] = sum_k Xh[m,k]*Wh[n,k] + bias[n]
// 256 threads = 8 warps (4m x 2n), warp tile 64x64.
// BK=64, 4-stage cp.async pipeline, ONE __syncthreads per K-chunk.
// ---------------------------------------------------------------------------
__global__ __launch_bounds__(THREADS, 1) void gemm_kernel(
        float* __restrict__ out, const float* __restrict__ bias) {
    extern __shared__ __half sm[];
    __half* Abase = sm;
    __half* Bbase = sm + STAGES * A_ST_H;

    const int tid = threadIdx.x;
    const int lane = tid & 31;
    const int warp = tid >> 5;
    const int m_off = (warp >> 1) * 64;     // 0,64,128,192
    const int n_off = (warp & 1) * 64;      // 0,64

    const int m0 = blockIdx.y * BM;
    const int n0 = blockIdx.x * BN;

    float acc[4][8][4];
#pragma unroll
    for (int i = 0; i < 4; i++)
#pragma unroll
        for (int j = 0; j < 8; j++)
#pragma unroll
            for (int c = 0; c < 4; c++) acc[i][j][c] = 0.0f;

    // stage loader: A 2048 chunks (256 rows x 8x16B), B 1024 chunks
    auto load_stage = [&](int s, int kt) {
        const int k0 = kt * BK;
        __half* As = Abase + s * A_ST_H;
        __half* Bs = Bbase + s * B_ST_H;
        const __half* Ag = g_Xh + (size_t)m0 * K_DIM + k0;
        const __half* Bg = g_Wh + (size_t)n0 * K_DIM + k0;
#pragma unroll
        for (int c = tid; c < 2048; c += THREADS) {
            int row = c >> 3, cg = c & 7;
            cp_async16(As + row * LDR + cg * 8, Ag + (size_t)row * K_DIM + cg * 8);
        }
#pragma unroll
        for (int c = tid; c < 1024; c += THREADS) {
            int row = c >> 3, cg = c & 7;
            cp_async16(Bs + row * LDR + cg * 8, Bg + (size_t)row * K_DIM + cg * 8);
        }
    };

    load_stage(0, 0); cp_commit();
    load_stage(1, 1); cp_commit();
    load_stage(2, 2); cp_commit();

    for (int kt = 0; kt < K_TILES; kt++) {
        const int s = kt % STAGES;
        // ensure chunk kt's group is complete; groups newer than kt still pending:
        // min(2, K_TILES-1-kt)
        if (kt >= K_TILES - 1)
            asm volatile("cp.async.wait_group 0;\n" ::: "memory");
        else if (kt == K_TILES - 2)
            asm volatile("cp.async.wait_group 1;\n" ::: "memory");
        else
            asm volatile("cp.async.wait_group 2;\n" ::: "memory");
        __syncthreads();
        // refill the stage consumed at iter kt-1 with chunk kt+3
        if (kt + 3 < K_TILES) { load_stage((kt + 3) % STAGES, kt + 3); cp_commit(); }

        const __half* As = Abase + s * A_ST_H;
        const __half* Bs = Bbase + s * B_ST_H;

#pragma unroll
        for (int kk = 0; kk < BK; kk += 16) {
            // A: 4 m16 tiles
            uint32_t afrag[4][4];
#pragma unroll
            for (int im = 0; im < 4; im++) {
                const __half* p = As + (m_off + im * 16 + (lane & 15)) * LDR +
                                  kk + (lane >> 4) * 8;
                ldsm_x4(afrag[im][0], afrag[im][1], afrag[im][2], afrag[im][3], p);
            }
            // B: 8 n8 tiles via 4 non-trans x4 loads (Bs is [n][k])
            uint32_t bfrag[8][2];
#pragma unroll
            for (int jp = 0; jp < 4; jp++) {
                int n_row = n_off + jp * 16 + (lane & 7) + ((lane >> 4) << 3);
                int k_col = kk + (((lane >> 3) & 1) << 3);
                const __half* p = Bs + n_row * LDR + k_col;
                ldsm_x4(bfrag[2 * jp][0], bfrag[2 * jp][1],
                        bfrag[2 * jp + 1][0], bfrag[2 * jp + 1][1], p);
            }
#pragma unroll
            for (int im = 0; im < 4; im++)
#pragma unroll
                for (int jn = 0; jn < 8; jn++)
                    mma_16816(acc[im][jn], afrag[im], bfrag[jn]);
        }
    }

    // epilogue: + bias, fp32 stores
    const int m_base = m0 + m_off;
    const int n_base = n0 + n_off;
#pragma unroll
    for (int jn = 0; jn < 8; jn++) {
        int col = n_base + jn * 8 + (lane & 3) * 2;
        float b0 = bias[col];
        float b1 = bias[col + 1];
#pragma unroll
        for (int im = 0; im < 4; im++) {
            int row0 = m_base + im * 16 + (lane >> 2);
            float2 v0 = make_float2(acc[im][jn][0] + b0, acc[im][jn][1] + b1);
            float2 v1 = make_float2(acc[im][jn][2] + b0, acc[im][jn][3] + b1);
            *reinterpret_cast<float2*>(&out[(size_t)row0 * N_DIM + col]) = v0;
            *reinterpret_cast<float2*>(&out[(size_t)(row0 + 8) * N_DIM + col]) = v1;
        }
    }
}

// ---------------------------------------------------------------------------
// Launch
// ---------------------------------------------------------------------------
extern "C" void kernel_launch(void* const* d_in, const int* in_sizes, int n_in,
                              void* d_out, int out_size) {
    const float* x      = (const float*)d_in[0];   // (4,2048,4096) f32
    const int*   packed = (const int*)d_in[1];     // (4096,2048) int32 bytes
    const float* absmax = (const float*)d_in[2];   // (4096,) f32
    const float* bias   = (const float*)d_in[3];   // (4096,) f32
    float* out = (float*)d_out;                    // (4,2048,4096) f32

    {   // x -> fp16
        int total = (M_DIM * K_DIM) / 4;
        convert_x_kernel<<<(total + 255) / 256, 256>>>(x);
    }
    {   // NF4 dequant -> fp16 W
        int total = N_DIM * (K_DIM / 2);
        dequant_kernel<<<(total + 255) / 256, 256>>>(packed, absmax);
    }
    {   // GEMM (idempotent host-side attr set; capture-safe)
        cudaFuncSetAttribute(gemm_kernel,
                             cudaFuncAttributeMaxDynamicSharedMemorySize, SMEM_BYTES);
        dim3 grid(N_DIM / BN, M_DIM / BM);         // (32, 32)
        gemm_kernel<<<grid, THREADS, SMEM_BYTES>>>(out, bias);
    }
}

// round 10
// speedup vs baseline: 1.2902x; 1.0931x over previous
#include <cuda_runtime.h>
#include <cuda_fp16.h>
#include <cstdint>

// Problem dims (fixed by the dataset)
#define M_DIM 8192      // 4 * 2048
#define N_DIM 4096      // OUT_FEATURES
#define K_DIM 4096      // IN_FEATURES

// GEMM tiling (mma.sync path — sm_103 base target, no tcgen05 available)
#define BM 128
#define BN 128
#define BK 64
#define LDS_PAD 8                     // halves of pad per row
#define LDR (BK + LDS_PAD)            // 72 halves = 144 B/row (16B aligned, conflict-free)
#define K_TILES (K_DIM / BK)          // 64
#define STAGES 3
#define THREADS 256                   // 8 warps: 2(m) x 4(n), warp tile 64x32

// Dynamic smem layout (halves)
#define A_ST_H (BM * LDR)             // 9216 halves = 18432 B
#define B_ST_H (BN * LDR)             // 9216 halves = 18432 B
#define SMEM_HALVES (STAGES * (A_ST_H + B_ST_H))     // 55296 halves
#define SMEM_BYTES (SMEM_HALVES * 2)                 // 110592 B  -> 2 CTAs/SM

// Scratch (allocation-free: __device__ globals)
__device__ __half g_Wh[(size_t)N_DIM * K_DIM];   // 32 MB, row-major [N][K]
__device__ __half g_Xh[(size_t)M_DIM * K_DIM];   // 64 MB, row-major [M][K]

__constant__ float c_nf4[16] = {
    -1.0f, -0.6961928009986877f, -0.5250730514526367f, -0.39491748809814453f,
    -0.28444138169288635f, -0.18477343022823334f, -0.09105003625154495f, 0.0f,
    0.07958029955625534f, 0.16093020141124725f, 0.24611230194568634f,
    0.33791524171829224f, 0.44070982933044434f, 0.5626170039176941f,
    0.7229568362236023f, 1.0f};

// ---------------------------------------------------------------------------
// Kernel 1 (fused prep): per thread idx in [0, 8388608):
//   - convert x[idx*4 .. idx*4+3] f32 -> g_Xh (same layout)
//   - dequant packed byte idx -> 2 halves of g_Wh
// Both index spaces are exactly M*K/4 == N*K/2 == 8,388,608.
// ---------------------------------------------------------------------------
__global__ void prep_kernel(const float* __restrict__ x,
                            const int* __restrict__ packed,
                            const float* __restrict__ absmax) {
    int idx = blockIdx.x * blockDim.x + threadIdx.x;
    if (idx >= (M_DIM * K_DIM) / 4) return;

    // x convert (16B read, 8B write)
    size_t i = (size_t)idx * 4;
    float4 v = *reinterpret_cast<const float4*>(x + i);
    __half2 h0 = __floats2half2_rn(v.x, v.y);
    __half2 h1 = __floats2half2_rn(v.z, v.w);
    uint2 o;
    o.x = *reinterpret_cast<const uint32_t*>(&h0);
    o.y = *reinterpret_cast<const uint32_t*>(&h1);
    *reinterpret_cast<uint2*>(&g_Xh[i]) = o;

    // NF4 dequant (4B read, 4B write); n = idx / (K/2)
    int n = idx >> 11;                       // K_DIM/2 = 2048
    int b = packed[idx];
    float a = absmax[n];
    __half2 w = __floats2half2_rn(c_nf4[(b >> 4) & 15] * a, c_nf4[b & 15] * a);
    *reinterpret_cast<__half2*>(&g_Wh[(size_t)idx * 2]) = w;
}

// ---------------------------------------------------------------------------
// mma.sync GEMM helpers
// ---------------------------------------------------------------------------
__device__ __forceinline__ void cp_async16(void* smem, const void* gmem) {
    uint32_t s = (uint32_t)__cvta_generic_to_shared(smem);
    asm volatile("cp.async.cg.shared.global [%0], [%1], 16;\n" :: "r"(s), "l"(gmem));
}
__device__ __forceinline__ void cp_commit() {
    asm volatile("cp.async.commit_group;\n" ::: "memory");
}
__device__ __forceinline__ void ldsm_x4(uint32_t& r0, uint32_t& r1, uint32_t& r2,
                                        uint32_t& r3, const void* p) {
    uint32_t a = (uint32_t)__cvta_generic_to_shared(p);
    asm volatile("ldmatrix.sync.aligned.m8n8.x4.shared.b16 {%0,%1,%2,%3}, [%4];\n"
                 : "=r"(r0), "=r"(r1), "=r"(r2), "=r"(r3) : "r"(a));
}
__device__ __forceinline__ void mma_16816(float* c, const uint32_t* a, const uint32_t* b) {
    asm volatile(
        "mma.sync.aligned.m16n8k16.row.col.f32.f16.f16.f32 "
        "{%0,%1,%2,%3}, {%4,%5,%6,%7}, {%8,%9}, {%0,%1,%2,%3};\n"
        : "+f"(c[0]), "+f"(c[1]), "+f"(c[2]), "+f"(c[3])
        : "r"(a[0]), "r"(a[1]), "r"(a[2]), "r"(a[3]), "r"(b[0]), "r"(b[1]));
}

// ---------------------------------------------------------------------------
// Kernel 2: GEMM  out[m,n] = sum_k Xh[m,k]*Wh[n,k] + bias[n]
// 256 threads = 8 warps (2m x 4n), warp tile 64x32.
// BK=64, 3-stage cp.async pipeline, occupancy 2 (prologue/epilogue overlap
// across co-resident CTAs).
// ---------------------------------------------------------------------------
__global__ __launch_bounds__(THREADS, 2) void gemm_kernel(
        float* __restrict__ out, const float* __restrict__ bias) {
    extern __shared__ __half sm[];
    __half* Abase = sm;
    __half* Bbase = sm + STAGES * A_ST_H;

    const int tid = threadIdx.x;
    const int lane = tid & 31;
    const int warp = tid >> 5;
    const int m_off = (warp >> 2) * 64;     // 0,64
    const int n_off = (warp & 3) * 32;      // 0,32,64,96

    const int m0 = blockIdx.y * BM;
    const int n0 = blockIdx.x * BN;

    float acc[4][4][4];
#pragma unroll
    for (int i = 0; i < 4; i++)
#pragma unroll
        for (int j = 0; j < 4; j++)
#pragma unroll
            for (int c = 0; c < 4; c++) acc[i][j][c] = 0.0f;

    // stage loader: A 1024 chunks (128 rows x 8x16B), B 1024 chunks
    auto load_stage = [&](int s, int kt) {
        const int k0 = kt * BK;
        __half* As = Abase + s * A_ST_H;
        __half* Bs = Bbase + s * B_ST_H;
        const __half* Ag = g_Xh + (size_t)m0 * K_DIM + k0;
        const __half* Bg = g_Wh + (size_t)n0 * K_DIM + k0;
#pragma unroll
        for (int c = tid; c < 1024; c += THREADS) {
            int row = c >> 3, cg = c & 7;
            cp_async16(As + row * LDR + cg * 8, Ag + (size_t)row * K_DIM + cg * 8);
        }
#pragma unroll
        for (int c = tid; c < 1024; c += THREADS) {
            int row = c >> 3, cg = c & 7;
            cp_async16(Bs + row * LDR + cg * 8, Bg + (size_t)row * K_DIM + cg * 8);
        }
    };

    load_stage(0, 0); cp_commit();
    load_stage(1, 1); cp_commit();

    for (int kt = 0; kt < K_TILES; kt++) {
        const int s = kt % STAGES;
        // committed groups so far: 0..kt+1 -> allow 1 newer (0 at the tail)
        if (kt == K_TILES - 1)
            asm volatile("cp.async.wait_group 0;\n" ::: "memory");
        else
            asm volatile("cp.async.wait_group 1;\n" ::: "memory");
        __syncthreads();
        // refill the stage consumed at iter kt-1 with chunk kt+2
        if (kt + 2 < K_TILES) { load_stage((kt + 2) % STAGES, kt + 2); cp_commit(); }

        const __half* As = Abase + s * A_ST_H;
        const __half* Bs = Bbase + s * B_ST_H;

#pragma unroll
        for (int kk = 0; kk < BK; kk += 16) {
            // A: 4 m16 tiles
            uint32_t afrag[4][4];
#pragma unroll
            for (int im = 0; im < 4; im++) {
                const __half* p = As + (m_off + im * 16 + (lane & 15)) * LDR +
                                  kk + (lane >> 4) * 8;
                ldsm_x4(afrag[im][0], afrag[im][1], afrag[im][2], afrag[im][3], p);
            }
            // B: 4 n8 tiles via 2 non-trans x4 loads (Bs is [n][k])
            uint32_t bfrag[4][2];
#pragma unroll
            for (int jp = 0; jp < 2; jp++) {
                int n_row = n_off + jp * 16 + (lane & 7) + ((lane >> 4) << 3);
                int k_col = kk + (((lane >> 3) & 1) << 3);
                const __half* p = Bs + n_row * LDR + k_col;
                ldsm_x4(bfrag[2 * jp][0], bfrag[2 * jp][1],
                        bfrag[2 * jp + 1][0], bfrag[2 * jp + 1][1], p);
            }
#pragma unroll
            for (int im = 0; im < 4; im++)
#pragma unroll
                for (int jn = 0; jn < 4; jn++)
                    mma_16816(acc[im][jn], afrag[im], bfrag[jn]);
        }
    }

    // epilogue: + bias, fp32 stores
    const int m_base = m0 + m_off;
    const int n_base = n0 + n_off;
#pragma unroll
    for (int jn = 0; jn < 4; jn++) {
        int col = n_base + jn * 8 + (lane & 3) * 2;
        float b0 = bias[col];
        float b1 = bias[col + 1];
#pragma unroll
        for (int im = 0; im < 4; im++) {
            int row0 = m_base + im * 16 + (lane >> 2);
            float2 v0 = make_float2(acc[im][jn][0] + b0, acc[im][jn][1] + b1);
            float2 v1 = make_float2(acc[im][jn][2] + b0, acc[im][jn][3] + b1);
            *reinterpret_cast<float2*>(&out[(size_t)row0 * N_DIM + col]) = v0;
            *reinterpret_cast<float2*>(&out[(size_t)(row0 + 8) * N_DIM + col]) = v1;
        }
    }
}

// ---------------------------------------------------------------------------
// Launch
// ---------------------------------------------------------------------------
extern "C" void kernel_launch(void* const* d_in, const int* in_sizes, int n_in,
                              void* d_out, int out_size) {
    const float* x      = (const float*)d_in[0];   // (4,2048,4096) f32
    const int*   packed = (const int*)d_in[1];     // (4096,2048) int32 bytes
    const float* absmax = (const float*)d_in[2];   // (4096,) f32
    const float* bias   = (const float*)d_in[3];   // (4096,) f32
    float* out = (float*)d_out;                    // (4,2048,4096) f32

    {   // fused x-convert + NF4 dequant
        int total = (M_DIM * K_DIM) / 4;           // == N*K/2 == 8,388,608
        prep_kernel<<<(total + 255) / 256, 256>>>(x, packed, absmax);
    }
    {   // GEMM (idempotent host-side attr set; capture-safe)
        cudaFuncSetAttribute(gemm_kernel,
                             cudaFuncAttributeMaxDynamicSharedMemorySize, SMEM_BYTES);
        dim3 grid(N_DIM / BN, M_DIM / BM);         // (32, 64)
        gemm_kernel<<<grid, THREADS, SMEM_BYTES>>>(out, bias);
    }
}